// round 11
// baseline (speedup 1.0000x reference)
#include <cuda_runtime.h>
#include <cfloat>

#define Bn 512
#define Tn 512
#define Kn 64
#define PD 4  // potentials prefetch ring depth per batch (registers)

__device__ int g_seq[Bn];

// Monotone float <-> uint order-preserving map (finite floats).
__device__ __forceinline__ unsigned fmap(float f) {
    const int i = __float_as_int(f);
    return (unsigned)(i ^ ((i >> 31) | 0x80000000));
}
__device__ __forceinline__ float funmap(unsigned u) {
    const int s = ~((int)u >> 31);
    return __int_as_float((int)(u ^ (0x80000000u | (unsigned)s)));
}

// ---------------------------------------------------------------------------
// Kernel 1: seq_lens[b] = int( mean_k( sum_t (x[b,t,k] != 0) ) )  (exact)
// ---------------------------------------------------------------------------
__global__ __launch_bounds__(256) void seqlen_kernel(const float* __restrict__ x) {
    __shared__ int red[256];
    const int b = blockIdx.x;
    const float4* xb = (const float4*)(x + (size_t)b * Tn * Kn);
    int c = 0;
    for (int i = threadIdx.x; i < (Tn * Kn) / 4; i += 256) {
        float4 v = xb[i];
        c += (v.x != 0.0f) + (v.y != 0.0f) + (v.z != 0.0f) + (v.w != 0.0f);
    }
    red[threadIdx.x] = c;
    __syncthreads();
    for (int s = 128; s > 0; s >>= 1) {
        if (threadIdx.x < s) red[threadIdx.x] += red[threadIdx.x + s];
        __syncthreads();
    }
    if (threadIdx.x == 0) g_seq[b] = red[0] >> 6;  // floor(total / 64)
}

// ---------------------------------------------------------------------------
// Exact full 64-candidate scan (general path). First max wins.
// ---------------------------------------------------------------------------
__device__ __noinline__ void full_scan64(
    float a_lo, float a_hi, const float2* trans2, int l,
    float& best0, float& best1, int& bi0, int& bi1)
{
    float b0 = -FLT_MAX, b1 = -FLT_MAX;
    int x0 = 0, x1 = 0;
#pragma unroll 4
    for (int i = 0; i < Kn; i++) {
        const float asel = (i < 32) ? a_lo : a_hi;
        const float av = __shfl_sync(0xffffffffu, asel, i & 31);
        const float2 tv = trans2[i * 32 + l];
        const float s0 = av + tv.x, s1 = av + tv.y;
        const bool g0 = s0 > b0; b0 = g0 ? s0 : b0; x0 = g0 ? i : x0;
        const bool g1 = s1 > b1; b1 = g1 ? s1 : b1; x1 = g1 ? i : x1;
    }
    best0 = b0; best1 = b1; bi0 = x0; bi1 = x1;
}

// Candidate fetch for a given batch's alpha pair.
#define FETCH_B(A_LO, A_HI, i_, s0_, s1_)                                   \
    {                                                                       \
        const float asel_ = ((i_) < 32) ? (A_LO) : (A_HI);                  \
        const float av_ = __shfl_sync(0xffffffffu, asel_, (i_) & 31);       \
        const float2 tv_ = trans2[(i_) * 32 + l];                           \
        s0_ = av_ + tv_.x;                                                  \
        s1_ = av_ + tv_.y;                                                  \
    }

// One DP step for one batch (fast path). Exact threshold (R8 semantics);
// FMNMX value tree + off-chain first-index recovery (bit-exact first-max).
#define STEP_B(T_, S_, A_LO, A_HI, M_LO, M_HI, PLO, PHI, PB, BPP)            \
    {                                                                        \
        const int t_ = (T_);                                                 \
        const float p_lo = PLO[S_];                                          \
        const float p_hi = PHI[S_];                                          \
        {                                                                    \
            const int tl_ = (t_ + PD <= Tn - 1) ? (t_ + PD) : (Tn - 1);      \
            PLO[S_] = PB[tl_ * Kn + l];                                      \
            PHI[S_] = PB[tl_ * Kn + 32 + l];                                 \
        }                                                                    \
        const unsigned long long M =                                         \
            ((unsigned long long)M_HI << 32) | (unsigned long long)M_LO;     \
        unsigned long long m_ = M;                                           \
        const int i0 = __ffsll((long long)m_) - 1;            m_ &= m_ - 1;  \
        const int i1 = m_ ? __ffsll((long long)m_) - 1 : i0;  m_ &= m_ - 1;  \
        const int i2 = m_ ? __ffsll((long long)m_) - 1 : i1;  m_ &= m_ - 1;  \
        const int i3 = m_ ? __ffsll((long long)m_) - 1 : i2;                 \
        unsigned long long Mrest = m_ & (m_ - 1);                            \
        float sa0, sb0, sa1, sb1, sa2, sb2, sa3, sb3;                        \
        FETCH_B(A_LO, A_HI, i0, sa0, sb0);                                   \
        FETCH_B(A_LO, A_HI, i1, sa1, sb1);                                   \
        FETCH_B(A_LO, A_HI, i2, sa2, sb2);                                   \
        FETCH_B(A_LO, A_HI, i3, sa3, sb3);                                   \
        float best0 = fmaxf(fmaxf(sa0, sa1), fmaxf(sa2, sa3));               \
        float best1 = fmaxf(fmaxf(sb0, sb1), fmaxf(sb2, sb3));               \
        int bi0 = i3, bi1 = i3;                                              \
        bi0 = (sa2 == best0) ? i2 : bi0;  bi1 = (sb2 == best1) ? i2 : bi1;   \
        bi0 = (sa1 == best0) ? i1 : bi0;  bi1 = (sb1 == best1) ? i1 : bi1;   \
        bi0 = (sa0 == best0) ? i0 : bi0;  bi1 = (sb0 == best1) ? i0 : bi1;   \
        if (Mrest) { /* rare C>4: continue ascending, strict > (exact) */    \
            do {                                                             \
                const int i_ = __ffsll((long long)Mrest) - 1;                \
                Mrest &= Mrest - 1;                                          \
                float s0_, s1_;                                              \
                FETCH_B(A_LO, A_HI, i_, s0_, s1_);                           \
                { const bool g = s0_ > best0;                                \
                  best0 = g ? s0_ : best0;  bi0 = g ? i_ : bi0; }            \
                { const bool g = s1_ > best1;                                \
                  best1 = g ? s1_ : best1;  bi1 = g ? i_ : bi1; }            \
            } while (Mrest);                                                 \
        }                                                                    \
        A_LO = p_lo + best0;                                                 \
        A_HI = p_hi + best1;                                                 \
        BPP[(t_ - 1) * 32 + l] =                                             \
            (unsigned short)((unsigned)bi0 | ((unsigned)bi1 << 8));          \
        const unsigned am_ = fmap(A_LO), ah_ = fmap(A_HI);                   \
        const unsigned wm_ =                                                 \
            __reduce_max_sync(0xffffffffu, am_ > ah_ ? am_ : ah_);           \
        const float thr_ = funmap(wm_) - rTp;                                \
        M_LO = __ballot_sync(0xffffffffu, A_LO >= thr_);                     \
        M_HI = __ballot_sync(0xffffffffu, A_HI >= thr_);                     \
    }

// Two batches interleaved in one warp: independent chains overlap latencies.
#define STEP2(T_, S_)                                                        \
    STEP_B(T_, S_, aA_lo, aA_hi, mA_lo, mA_hi, pAlo, pAhi, pbA, bpA)         \
    STEP_B(T_, S_, aB_lo, aB_hi, mB_lo, mB_hi, pBlo, pBhi, pbB, bpB)

// ---------------------------------------------------------------------------
// Kernel 2: single-warp, TWO-batch Viterbi with exact-threshold pruning.
// ---------------------------------------------------------------------------
__global__ __launch_bounds__(32) void viterbi_kernel(
    const float* __restrict__ pots,   // [B, T, K]
    const float* __restrict__ trans,  // [K, K]
    float* __restrict__ out)          // [B, T] float32
{
    extern __shared__ char dyn_smem[];
    float2* trans2 = (float2*)dyn_smem;                              // 16384 B
    unsigned short* bpA = (unsigned short*)(dyn_smem + 16384);       // 32704 B
    unsigned short* bpB = (unsigned short*)(dyn_smem + 16384 + 32704);
    __shared__ unsigned char tags[2][Tn];
    __shared__ float alpha_f[2][Kn];

    const int b0 = 2 * blockIdx.x;
    const int l = threadIdx.x;  // lane; owns to-tags l and l+32 (both batches)

    // ---- Prologue: stage transitions (float2-packed) + padded range ----
    const float4* tr4 = (const float4*)trans;
    float tmin = FLT_MAX, tmax = -FLT_MAX;
#pragma unroll
    for (int q = 0; q < 32; q++) {
        const int idx = q * 32 + l;
        const float4 v = tr4[idx];
        tmin = fminf(tmin, fminf(fminf(v.x, v.y), fminf(v.z, v.w)));
        tmax = fmaxf(tmax, fmaxf(fmaxf(v.x, v.y), fmaxf(v.z, v.w)));
        const int base = idx * 4;
        const int i = base >> 6;
        const int c = base & 63;
        if (c < 32) {
            trans2[i * 32 + c + 0].x = v.x;
            trans2[i * 32 + c + 1].x = v.y;
            trans2[i * 32 + c + 2].x = v.z;
            trans2[i * 32 + c + 3].x = v.w;
        } else {
            const int cc = c - 32;
            trans2[i * 32 + cc + 0].y = v.x;
            trans2[i * 32 + cc + 1].y = v.y;
            trans2[i * 32 + cc + 2].y = v.z;
            trans2[i * 32 + cc + 3].y = v.w;
        }
    }
    const unsigned rmn = __reduce_min_sync(0xffffffffu, fmap(tmin));
    const unsigned rmx = __reduce_max_sync(0xffffffffu, fmap(tmax));
    const float r = funmap(rmx) - funmap(rmn);
    const float rTp = r + fabsf(r) * 1e-5f + 0.01f;  // pad only ADDS candidates
    __syncwarp();

    const float* pbA = pots + (size_t)b0 * Tn * Kn;
    const float* pbB = pbA + (size_t)Tn * Kn;
    int slA = g_seq[b0];      if (slA > Tn) slA = Tn;
    int slB = g_seq[b0 + 1];  if (slB > Tn) slB = Tn;

    float aA_lo = pbA[l],      aA_hi = pbA[32 + l];
    float aB_lo = pbB[l],      aB_hi = pbB[32 + l];

    if (slA >= Tn && slB >= Tn) {
        // ---------------- FAST PATH: every step active, both batches --------
        unsigned mA_lo, mA_hi, mB_lo, mB_hi;
        {
            const unsigned amA = fmap(aA_lo), ahA = fmap(aA_hi);
            const unsigned wmA = __reduce_max_sync(0xffffffffu, amA > ahA ? amA : ahA);
            const float thrA = funmap(wmA) - rTp;
            mA_lo = __ballot_sync(0xffffffffu, aA_lo >= thrA);
            mA_hi = __ballot_sync(0xffffffffu, aA_hi >= thrA);
            const unsigned amB = fmap(aB_lo), ahB = fmap(aB_hi);
            const unsigned wmB = __reduce_max_sync(0xffffffffu, amB > ahB ? amB : ahB);
            const float thrB = funmap(wmB) - rTp;
            mB_lo = __ballot_sync(0xffffffffu, aB_lo >= thrB);
            mB_hi = __ballot_sync(0xffffffffu, aB_hi >= thrB);
        }
        float pAlo[PD], pAhi[PD], pBlo[PD], pBhi[PD];
#pragma unroll
        for (int d = 1; d <= PD; d++) {
            pAlo[d & (PD - 1)] = pbA[d * Kn + l];
            pAhi[d & (PD - 1)] = pbA[d * Kn + 32 + l];
            pBlo[d & (PD - 1)] = pbB[d * Kn + l];
            pBhi[d & (PD - 1)] = pbB[d * Kn + 32 + l];
        }
        // t = 1..511: 127 blocks of 4 (t=1..508) + 3 remainder.
        int t = 1;
#pragma unroll 1
        for (int tb = 0; tb < 127; tb++) {
            STEP2(t + 0, 1); STEP2(t + 1, 2); STEP2(t + 2, 3); STEP2(t + 3, 0);
            t += 4;
        }
        STEP2(t + 0, 1); STEP2(t + 1, 2); STEP2(t + 2, 3);
    } else {
        // ---------------- GENERAL PATH (rare): exact full scan, per batch ---
#pragma unroll 1
        for (int t = 1; t < Tn; t++) {
            if (t < slA) {
                float b0v, b1v; int x0, x1;
                full_scan64(aA_lo, aA_hi, trans2, l, b0v, b1v, x0, x1);
                aA_lo = pbA[t * Kn + l] + b0v;
                aA_hi = pbA[t * Kn + 32 + l] + b1v;
                bpA[(t - 1) * 32 + l] =
                    (unsigned short)((unsigned)x0 | ((unsigned)x1 << 8));
            } else {
                bpA[(t - 1) * 32 + l] =
                    (unsigned short)((unsigned)l | ((unsigned)(32 + l) << 8));
            }
            if (t < slB) {
                float b0v, b1v; int x0, x1;
                full_scan64(aB_lo, aB_hi, trans2, l, b0v, b1v, x0, x1);
                aB_lo = pbB[t * Kn + l] + b0v;
                aB_hi = pbB[t * Kn + 32 + l] + b1v;
                bpB[(t - 1) * 32 + l] =
                    (unsigned short)((unsigned)x0 | ((unsigned)x1 << 8));
            } else {
                bpB[(t - 1) * 32 + l] =
                    (unsigned short)((unsigned)l | ((unsigned)(32 + l) << 8));
            }
        }
    }

    // Final alphas -> smem
    alpha_f[0][l] = aA_lo;  alpha_f[0][32 + l] = aA_hi;
    alpha_f[1][l] = aB_lo;  alpha_f[1][32 + l] = aB_hi;
    __syncwarp();

    // Backtrace: lanes 0 and 1 run the two batches concurrently.
    if (l < 2) {
        const unsigned short* bp = l ? bpB : bpA;
        float bv = alpha_f[l][0];
        int bt = 0;
#pragma unroll 1
        for (int i = 1; i < Kn; i++) {
            const float v = alpha_f[l][i];
            if (v > bv) { bv = v; bt = i; }   // first max wins
        }
        int tg = bt;
        tags[l][Tn - 1] = (unsigned char)tg;
#pragma unroll 1
        for (int tt = Tn - 2; tt >= 0; tt--) {
            const unsigned v = bp[tt * 32 + (tg & 31)];
            tg = (int)((v >> ((tg >> 5) * 8)) & 0xffu);
            tags[l][tt] = (unsigned char)tg;
        }
    }
    __syncwarp();

    // Coalesced float32 output writes for both batches.
    float* obA = out + (size_t)b0 * Tn;
    float* obB = obA + Tn;
#pragma unroll
    for (int tt = l; tt < Tn; tt += 32) {
        obA[tt] = (float)tags[0][tt];
        obB[tt] = (float)tags[1][tt];
    }
}

// ---------------------------------------------------------------------------
extern "C" void kernel_launch(void* const* d_in, const int* in_sizes, int n_in,
                              void* d_out, int out_size) {
    const float* inputs = nullptr;
    const float* transitions = nullptr;
    for (int i = 0; i < n_in; i++) {
        if (in_sizes[i] == Kn * Kn) transitions = (const float*)d_in[i];
        else if (in_sizes[i] == Bn * Tn * Kn) inputs = (const float*)d_in[i];
    }
    if (!inputs) inputs = (const float*)d_in[0];
    if (!transitions) transitions = (const float*)d_in[1];

    float* out = (float*)d_out;

    const int dyn_bytes = 16384 + 2 * (Tn - 1) * 32 * (int)sizeof(unsigned short);
    // Host-side config call, capture-safe (proven R5+).
    cudaFuncSetAttribute(viterbi_kernel,
                         cudaFuncAttributeMaxDynamicSharedMemorySize, dyn_bytes);

    seqlen_kernel<<<Bn, 256>>>(inputs);
    viterbi_kernel<<<Bn / 2, 32, dyn_bytes>>>(inputs, transitions, out);
}

// round 12
// speedup vs baseline: 1.4505x; 1.4505x over previous
#include <cuda_runtime.h>
#include <cfloat>

#define Bn 512
#define Tn 512
#define Kn 64
#define PD 8  // potentials prefetch ring depth (registers)

__device__ int g_seq[Bn];

// Monotone float <-> uint order-preserving map (finite floats).
__device__ __forceinline__ unsigned fmap(float f) {
    const int i = __float_as_int(f);
    return (unsigned)(i ^ ((i >> 31) | 0x80000000));
}
__device__ __forceinline__ float funmap(unsigned u) {
    const int s = ~((int)u >> 31);
    return __int_as_float((int)(u ^ (0x80000000u | (unsigned)s)));
}

// Warp-wide max via shfl butterfly (known-latency path: 5 x (SHFL+IMNMX)).
__device__ __forceinline__ unsigned warpmax_bfly(unsigned v) {
    unsigned w;
    w = __shfl_xor_sync(0xffffffffu, v, 16); v = v > w ? v : w;
    w = __shfl_xor_sync(0xffffffffu, v, 8);  v = v > w ? v : w;
    w = __shfl_xor_sync(0xffffffffu, v, 4);  v = v > w ? v : w;
    w = __shfl_xor_sync(0xffffffffu, v, 2);  v = v > w ? v : w;
    w = __shfl_xor_sync(0xffffffffu, v, 1);  v = v > w ? v : w;
    return v;
}

// ---------------------------------------------------------------------------
// Kernel 1: seq_lens[b] = int( mean_k( sum_t (x[b,t,k] != 0) ) )  (exact)
// ---------------------------------------------------------------------------
__global__ __launch_bounds__(256) void seqlen_kernel(const float* __restrict__ x) {
    __shared__ int red[256];
    const int b = blockIdx.x;
    const float4* xb = (const float4*)(x + (size_t)b * Tn * Kn);
    int c = 0;
    for (int i = threadIdx.x; i < (Tn * Kn) / 4; i += 256) {
        float4 v = xb[i];
        c += (v.x != 0.0f) + (v.y != 0.0f) + (v.z != 0.0f) + (v.w != 0.0f);
    }
    red[threadIdx.x] = c;
    __syncthreads();
    for (int s = 128; s > 0; s >>= 1) {
        if (threadIdx.x < s) red[threadIdx.x] += red[threadIdx.x + s];
        __syncthreads();
    }
    if (threadIdx.x == 0) g_seq[b] = red[0] >> 6;  // floor(total / 64)
}

// ---------------------------------------------------------------------------
// Exact full 64-candidate scan (general path). First max wins.
// ---------------------------------------------------------------------------
__device__ __noinline__ void full_scan64(
    float a_lo, float a_hi, const float2* trans2, int l,
    float& best0, float& best1, int& bi0, int& bi1)
{
    float b0 = -FLT_MAX, b1 = -FLT_MAX;
    int x0 = 0, x1 = 0;
#pragma unroll 4
    for (int i = 0; i < Kn; i++) {
        const float asel = (i < 32) ? a_lo : a_hi;
        const float av = __shfl_sync(0xffffffffu, asel, i & 31);
        const float2 tv = trans2[i * 32 + l];
        const float s0 = av + tv.x, s1 = av + tv.y;
        const bool g0 = s0 > b0; b0 = g0 ? s0 : b0; x0 = g0 ? i : x0;
        const bool g1 = s1 > b1; b1 = g1 ? s1 : b1; x1 = g1 ? i : x1;
    }
    best0 = b0; best1 = b1; bi0 = x0; bi1 = x1;
}

// Candidate fetch: alpha[i] via shuffle (uniform lane), trans column pair.
#define FETCH(i_, s0_, s1_)                                                 \
    {                                                                       \
        const float asel_ = ((i_) < 32) ? a_lo : a_hi;                      \
        const float av_ = __shfl_sync(0xffffffffu, asel_, (i_) & 31);       \
        const float2 tv_ = trans2[(i_) * 32 + l];                           \
        s0_ = av_ + tv_.x;                                                  \
        s1_ = av_ + tv_.y;                                                  \
    }

// One DP step (fast path, t < sl guaranteed). Ring slot S_ is compile-time.
// EXACT threshold; warp max via shfl butterfly (A/B vs REDUX in R10).
#define STEP_F(T_, S_)                                                       \
    {                                                                        \
        const int t_ = (T_);                                                 \
        const float p_lo = plo[S_];                                          \
        const float p_hi = phi[S_];                                          \
        {                                                                    \
            const int tl_ = (t_ + PD <= Tn - 1) ? (t_ + PD) : (Tn - 1);      \
            plo[S_] = pb[tl_ * Kn + l];                                      \
            phi[S_] = pb[tl_ * Kn + 32 + l];                                 \
        }                                                                    \
        const unsigned long long M =                                         \
            ((unsigned long long)m_hi << 32) | (unsigned long long)m_lo;     \
        /* 4 lowest candidates, ascending, duplicate-padded when C<4 */      \
        unsigned long long m_ = M;                                           \
        const int i0 = __ffsll((long long)m_) - 1;            m_ &= m_ - 1;  \
        const int i1 = m_ ? __ffsll((long long)m_) - 1 : i0;  m_ &= m_ - 1;  \
        const int i2 = m_ ? __ffsll((long long)m_) - 1 : i1;  m_ &= m_ - 1;  \
        const int i3 = m_ ? __ffsll((long long)m_) - 1 : i2;                 \
        unsigned long long Mrest = m_ & (m_ - 1);                            \
        float sa0, sb0, sa1, sb1, sa2, sb2, sa3, sb3;                        \
        FETCH(i0, sa0, sb0); FETCH(i1, sa1, sb1);                            \
        FETCH(i2, sa2, sb2); FETCH(i3, sa3, sb3);                            \
        /* FMNMX tree: best is bitwise one of the candidates */              \
        float best0 = fmaxf(fmaxf(sa0, sa1), fmaxf(sa2, sa3));               \
        float best1 = fmaxf(fmaxf(sb0, sb1), fmaxf(sb2, sb3));               \
        /* OFF-CHAIN index recovery: descending, i0 last -> smallest index   \
           among value-ties wins == jnp.argmax first-max (exact) */          \
        int bi0 = i3, bi1 = i3;                                              \
        bi0 = (sa2 == best0) ? i2 : bi0;  bi1 = (sb2 == best1) ? i2 : bi1;   \
        bi0 = (sa1 == best0) ? i1 : bi0;  bi1 = (sb1 == best1) ? i1 : bi1;   \
        bi0 = (sa0 == best0) ? i0 : bi0;  bi1 = (sb0 == best1) ? i0 : bi1;   \
        if (Mrest) { /* rare: C > 4; continue ascending, strict > (exact) */ \
            do {                                                             \
                const int i_ = __ffsll((long long)Mrest) - 1;                \
                Mrest &= Mrest - 1;                                          \
                float s0_, s1_;                                              \
                FETCH(i_, s0_, s1_);                                         \
                { const bool g = s0_ > best0;                                \
                  best0 = g ? s0_ : best0;  bi0 = g ? i_ : bi0; }            \
                { const bool g = s1_ > best1;                                \
                  best1 = g ? s1_ : best1;  bi1 = g ? i_ : bi1; }            \
            } while (Mrest);                                                 \
        }                                                                    \
        a_lo = p_lo + best0;                                                 \
        a_hi = p_hi + best1;                                                 \
        /* packed backpointer store: one STS.16 per lane (off-chain) */      \
        bp16[(t_ - 1) * 32 + l] =                                            \
            (unsigned short)((unsigned)bi0 | ((unsigned)bi1 << 8));          \
        /* EXACT threshold via shfl-butterfly max (A/B vs REDUX) */          \
        const unsigned am_ = fmap(a_lo), ah_ = fmap(a_hi);                   \
        const unsigned wm_ = warpmax_bfly(am_ > ah_ ? am_ : ah_);            \
        const float thr_ = funmap(wm_) - rTp;                                \
        m_lo = __ballot_sync(0xffffffffu, a_lo >= thr_);                     \
        m_hi = __ballot_sync(0xffffffffu, a_hi >= thr_);                     \
    }

// ---------------------------------------------------------------------------
// Kernel 2: single-warp Viterbi, exact-threshold pruned step.
// Candidates = { i : alpha[i] >= max(alpha) - rTp }; excluded i lose STRICTLY
// for every to-tag, so first-max over candidates == full jnp.argmax.
// ---------------------------------------------------------------------------
__global__ __launch_bounds__(32) void viterbi_kernel(
    const float* __restrict__ pots,   // [B, T, K]
    const float* __restrict__ trans,  // [K, K]
    float* __restrict__ out)          // [B, T] float32
{
    extern __shared__ float2 trans2[];              // [64][32]: (T[i][l], T[i][l+32])
    __shared__ unsigned short bp16[(Tn - 1) * 32];  // packed (bi0 | bi1<<8)
    __shared__ unsigned char tags[Tn];
    __shared__ float alpha_f[Kn];

    const int b = blockIdx.x;
    const int l = threadIdx.x;  // lane; owns to-tags l and l+32

    // ---- Prologue: stage transitions (float2-packed) + padded range ----
    const float4* tr4 = (const float4*)trans;
    float tmin = FLT_MAX, tmax = -FLT_MAX;
#pragma unroll
    for (int q = 0; q < 32; q++) {
        const int idx = q * 32 + l;
        const float4 v = tr4[idx];
        tmin = fminf(tmin, fminf(fminf(v.x, v.y), fminf(v.z, v.w)));
        tmax = fmaxf(tmax, fmaxf(fmaxf(v.x, v.y), fmaxf(v.z, v.w)));
        const int base = idx * 4;
        const int i = base >> 6;
        const int c = base & 63;
        if (c < 32) {
            trans2[i * 32 + c + 0].x = v.x;
            trans2[i * 32 + c + 1].x = v.y;
            trans2[i * 32 + c + 2].x = v.z;
            trans2[i * 32 + c + 3].x = v.w;
        } else {
            const int cc = c - 32;
            trans2[i * 32 + cc + 0].y = v.x;
            trans2[i * 32 + cc + 1].y = v.y;
            trans2[i * 32 + cc + 2].y = v.z;
            trans2[i * 32 + cc + 3].y = v.w;
        }
    }
    const unsigned rmn_neg = warpmax_bfly(~fmap(tmin));  // max of ~u == min of u
    const unsigned rmx = warpmax_bfly(fmap(tmax));
    const float r = funmap(rmx) - funmap(~rmn_neg);
    const float rTp = r + fabsf(r) * 1e-5f + 0.01f;  // pad only ADDS candidates
    __syncwarp();

    const float* pb = pots + (size_t)b * Tn * Kn;
    int sl = g_seq[b];
    if (sl > Tn) sl = Tn;

    float a_lo = pb[l];
    float a_hi = pb[32 + l];

    if (sl >= Tn) {
        // ---------------- FAST PATH: every step active ----------------------
        unsigned m_lo, m_hi;
        {
            const unsigned am = fmap(a_lo), ah = fmap(a_hi);
            const unsigned wm = warpmax_bfly(am > ah ? am : ah);
            const float thr = funmap(wm) - rTp;
            m_lo = __ballot_sync(0xffffffffu, a_lo >= thr);
            m_hi = __ballot_sync(0xffffffffu, a_hi >= thr);
        }
        float plo[PD], phi[PD];
#pragma unroll
        for (int d = 1; d <= PD; d++) {
            plo[d & (PD - 1)] = pb[d * Kn + l];
            phi[d & (PD - 1)] = pb[d * Kn + 32 + l];
        }
        int t = 1;
#pragma unroll 1
        for (int tb = 0; tb < 63; tb++) {
            STEP_F(t + 0, 1); STEP_F(t + 1, 2); STEP_F(t + 2, 3); STEP_F(t + 3, 4);
            STEP_F(t + 4, 5); STEP_F(t + 5, 6); STEP_F(t + 6, 7); STEP_F(t + 7, 0);
            t += 8;
        }
        STEP_F(t + 0, 1); STEP_F(t + 1, 2); STEP_F(t + 2, 3); STEP_F(t + 3, 4);
        STEP_F(t + 4, 5); STEP_F(t + 5, 6); STEP_F(t + 6, 7);
    } else {
        // ---------------- GENERAL PATH (rare): exact full scan ---------------
#pragma unroll 1
        for (int t = 1; t < Tn; t++) {
            if (t < sl) {
                float best0, best1; int bi0, bi1;
                full_scan64(a_lo, a_hi, trans2, l, best0, best1, bi0, bi1);
                a_lo = pb[t * Kn + l] + best0;
                a_hi = pb[t * Kn + 32 + l] + best1;
                bp16[(t - 1) * 32 + l] =
                    (unsigned short)((unsigned)bi0 | ((unsigned)bi1 << 8));
            } else {
                bp16[(t - 1) * 32 + l] =
                    (unsigned short)((unsigned)l | ((unsigned)(32 + l) << 8));
            }
        }
    }

    // Final alpha -> smem for the backtrace scan
    alpha_f[l] = a_lo;
    alpha_f[32 + l] = a_hi;
    __syncwarp();

    // Backtrace (smem pointer-chase) by lane 0. First max wins.
    if (l == 0) {
        float bv = alpha_f[0];
        int bt = 0;
#pragma unroll 1
        for (int i = 1; i < Kn; i++) {
            const float v = alpha_f[i];
            if (v > bv) { bv = v; bt = i; }
        }
        int tg = bt;
        tags[Tn - 1] = (unsigned char)tg;
#pragma unroll 1
        for (int tt = Tn - 2; tt >= 0; tt--) {
            const unsigned v = bp16[tt * 32 + (tg & 31)];
            tg = (int)((v >> ((tg >> 5) * 8)) & 0xffu);
            tags[tt] = (unsigned char)tg;
        }
    }
    __syncwarp();

    // Coalesced float32 output write (16 per lane).
    float* ob = out + (size_t)b * Tn;
#pragma unroll
    for (int tt = l; tt < Tn; tt += 32) ob[tt] = (float)tags[tt];
}

// ---------------------------------------------------------------------------
extern "C" void kernel_launch(void* const* d_in, const int* in_sizes, int n_in,
                              void* d_out, int out_size) {
    const float* inputs = nullptr;
    const float* transitions = nullptr;
    for (int i = 0; i < n_in; i++) {
        if (in_sizes[i] == Kn * Kn) transitions = (const float*)d_in[i];
        else if (in_sizes[i] == Bn * Tn * Kn) inputs = (const float*)d_in[i];
    }
    if (!inputs) inputs = (const float*)d_in[0];
    if (!transitions) transitions = (const float*)d_in[1];

    float* out = (float*)d_out;

    // Static (~33.5 KB) + 16 KB dynamic -> opt in (host config, capture-safe).
    cudaFuncSetAttribute(viterbi_kernel,
                         cudaFuncAttributeMaxDynamicSharedMemorySize,
                         Kn * 32 * (int)sizeof(float2));

    seqlen_kernel<<<Bn, 256>>>(inputs);
    viterbi_kernel<<<Bn, 32, Kn * 32 * sizeof(float2)>>>(inputs, transitions, out);
}